// round 5
// baseline (speedup 1.0000x reference)
#include <cuda_runtime.h>
#include <cstdint>

#define NN 100000
#define DD 64
#define EE 1600000

// Scratch (__device__ globals per allocation-free rule).
__device__ float g_bufA[NN * DD];   // 25.6 MB
__device__ float g_bufB[NN * DD];
__device__ int   g_deg   [NN];
__device__ int   g_rowptr[NN + 1];
__device__ int   g_cursor[NN];
__device__ int   g_col   [EE];

// ---------------------------------------------------------------------------
// f32x2 packed helpers (sm_100+; FFMA2 only reachable via PTX)
// ---------------------------------------------------------------------------
typedef unsigned long long ull;
__device__ __forceinline__ ull pack2(float a, float b) {
    ull r; asm("mov.b64 %0, {%1, %2};" : "=l"(r) : "f"(a), "f"(b)); return r;
}
__device__ __forceinline__ void unpack2(ull v, float& a, float& b) {
    asm("mov.b64 {%0, %1}, %2;" : "=f"(a), "=f"(b) : "l"(v));
}
__device__ __forceinline__ ull fma2(ull a, ull b, ull c) {
    ull r; asm("fma.rn.f32x2 %0, %1, %2, %3;" : "=l"(r) : "l"(a), "l"(b), "l"(c)); return r;
}

// ---------------------------------------------------------------------------
// CSR build: zero -> histogram(dst) -> exclusive scan -> fill(col by cursor)
// ---------------------------------------------------------------------------
__global__ void zero_deg_kernel() {
    int i = blockIdx.x * blockDim.x + threadIdx.x;
    if (i < NN) g_deg[i] = 0;
}

__global__ void hist_kernel(const int* __restrict__ ei) {
    int e = blockIdx.x * blockDim.x + threadIdx.x;
    if (e < EE) atomicAdd(&g_deg[ei[EE + e]], 1);
}

// Single-CTA two-level scan: 1024 threads, each owns a 98-element chunk.
__global__ void scan_kernel() {
    __shared__ int sums[1024];
    const int CH = (NN + 1023) / 1024;   // 98
    int t = threadIdx.x;
    int base = t * CH;
    int s = 0;
    for (int i = 0; i < CH; i++) {
        int idx = base + i;
        if (idx < NN) s += g_deg[idx];
    }
    sums[t] = s;
    __syncthreads();
    for (int off = 1; off < 1024; off <<= 1) {
        int v = (t >= off) ? sums[t - off] : 0;
        __syncthreads();
        sums[t] += v;
        __syncthreads();
    }
    int prefix = (t == 0) ? 0 : sums[t - 1];
    for (int i = 0; i < CH; i++) {
        int idx = base + i;
        if (idx < NN) {
            int d = g_deg[idx];
            g_rowptr[idx] = prefix;
            g_cursor[idx] = prefix;
            prefix += d;
        }
    }
    if (t == 1023) g_rowptr[NN] = prefix;   // == EE
}

__global__ void fill_kernel(const int* __restrict__ ei) {
    int e = blockIdx.x * blockDim.x + threadIdx.x;
    if (e < EE) {
        int d = ei[EE + e];
        int p = atomicAdd(&g_cursor[d], 1);
        g_col[p] = ei[e];
    }
}

// ---------------------------------------------------------------------------
// Fused block kernel: [CSR gather-agg] -> stage(smem) -> MLP -> out.
// 8 warps/CTA, warp handles 32 rows. Lane owns one full row for the MLP.
// GEMM computed in 32-col half-passes: acc[16] packed f32x2 (32 regs) so
// register peak stays ~95 < the 128 cap from __launch_bounds__(256,2).
// ---------------------------------------------------------------------------
#define STRIDE 66                           // 8B-aligned pairs; 2-way conflict max
#define STAGE_WORDS (32 * STRIDE)
#define SMEM_TOTAL_WORDS (2 * DD * DD + 8 * STAGE_WORDS)

// One 32-column half of a [64x64] GEMM: acc[j] covers cols (half*32+2j, +1).
__device__ __forceinline__ void half_gemm(const float* __restrict__ ws,
                                          const float* __restrict__ h,
                                          ull* acc, int half) {
#pragma unroll 2
    for (int k = 0; k < DD; k++) {
        float hk = h[k];
        ull h2 = pack2(hk, hk);
#pragma unroll
        for (int jj = 0; jj < 8; jj++) {
            float4 wv = *reinterpret_cast<const float4*>(ws + k * DD + half * 32 + jj * 4);
            acc[2 * jj]     = fma2(pack2(wv.x, wv.y), h2, acc[2 * jj]);
            acc[2 * jj + 1] = fma2(pack2(wv.z, wv.w), h2, acc[2 * jj + 1]);
        }
    }
}

template <bool AGG, bool TWO, bool RELU_OUT>
__global__ __launch_bounds__(256, 2) void block_kernel(
        const float* __restrict__ in, float* __restrict__ out,
        const float* __restrict__ w1, const float* __restrict__ b1,
        const float* __restrict__ w2, const float* __restrict__ b2) {
    extern __shared__ float sm[];
    float* ws1 = sm;
    float* ws2 = sm + DD * DD;
    int tid  = threadIdx.x;
    int lane = tid & 31;
    int warp = tid >> 5;
    float* stg = sm + 2 * DD * DD + warp * STAGE_WORDS;

    // stage weights (coalesced, all 256 threads)
    for (int i = tid; i < DD * DD; i += 256) {
        ws1[i] = w1[i];
        if (TWO) ws2[i] = w2[i];
    }

    // gather + stage: warp fills its 32 rows (self term + CSR neighbor sum)
    int rowbase = blockIdx.x * 256 + warp * 32;
    for (int r = 0; r < 32; r++) {
        int row = rowbase + r;
        float2 a = make_float2(0.f, 0.f);
        if (row < NN) {
            a = *reinterpret_cast<const float2*>(in + (size_t)row * DD + 2 * lane);
            if (AGG) {
                int start = g_rowptr[row];
                int end   = g_rowptr[row + 1];
                for (int i = start; i < end; i += 32) {
                    int n   = min(32, end - i);
                    int idx = (i + lane < end) ? g_col[i + lane] : 0;
                    for (int j = 0; j < n; j++) {
                        int s = __shfl_sync(0xffffffffu, idx, j);
                        float2 v = *reinterpret_cast<const float2*>(
                            in + (size_t)s * DD + 2 * lane);
                        a.x += v.x; a.y += v.y;
                    }
                }
            }
        }
        *reinterpret_cast<float2*>(stg + r * STRIDE + 2 * lane) = a;
    }
    __syncthreads();

    float* hrow = stg + lane * STRIDE;   // this lane's row (warp-private stage)
    const ull* b1u = reinterpret_cast<const ull*>(b1);

    // GEMM1, both halves kept in registers until h can be overwritten
    ull mA[16], mB[16];
#pragma unroll
    for (int j = 0; j < 16; j++) mA[j] = b1u[j];
    half_gemm(ws1, hrow, mA, 0);
#pragma unroll
    for (int j = 0; j < 16; j++) mB[j] = b1u[16 + j];
    half_gemm(ws1, hrow, mB, 1);

    if (TWO) {
        // relu(m) -> overwrite own stage row (h dead now); lane-private, no sync
#pragma unroll
        for (int j = 0; j < 16; j++) {
            float a, b;
            unpack2(mA[j], a, b);
            *reinterpret_cast<float2*>(hrow + 2 * j) =
                make_float2(fmaxf(a, 0.f), fmaxf(b, 0.f));
            unpack2(mB[j], a, b);
            *reinterpret_cast<float2*>(hrow + 32 + 2 * j) =
                make_float2(fmaxf(a, 0.f), fmaxf(b, 0.f));
        }
        const ull* b2u = reinterpret_cast<const ull*>(b2);
#pragma unroll
        for (int j = 0; j < 16; j++) mA[j] = b2u[j];
        half_gemm(ws2, hrow, mA, 0);
#pragma unroll
        for (int j = 0; j < 16; j++) mB[j] = b2u[16 + j];
        half_gemm(ws2, hrow, mB, 1);
    }

    // epilogue: optional relu, write to own row, transpose, coalesced store
#pragma unroll
    for (int j = 0; j < 16; j++) {
        float a, b;
        unpack2(mA[j], a, b);
        if (RELU_OUT) { a = fmaxf(a, 0.f); b = fmaxf(b, 0.f); }
        *reinterpret_cast<float2*>(hrow + 2 * j) = make_float2(a, b);
        unpack2(mB[j], a, b);
        if (RELU_OUT) { a = fmaxf(a, 0.f); b = fmaxf(b, 0.f); }
        *reinterpret_cast<float2*>(hrow + 32 + 2 * j) = make_float2(a, b);
    }
    __syncwarp();
#pragma unroll 4
    for (int r = 0; r < 32; r++) {
        int row = rowbase + r;
        if (row < NN) {
            float2 v = *reinterpret_cast<const float2*>(stg + r * STRIDE + 2 * lane);
            *reinterpret_cast<float2*>(out + (size_t)row * DD + 2 * lane) = v;
        }
    }
}

// ---------------------------------------------------------------------------
// Launch
// ---------------------------------------------------------------------------
extern "C" void kernel_launch(void* const* d_in, const int* in_sizes, int n_in,
                              void* d_out, int out_size) {
    const float* x  = (const float*)d_in[0];
    const int*   ei = (const int*)d_in[1];
    const float* w1[3] = {(const float*)d_in[2], (const float*)d_in[6],  (const float*)d_in[10]};
    const float* b1[3] = {(const float*)d_in[3], (const float*)d_in[7],  (const float*)d_in[11]};
    const float* w2[3] = {(const float*)d_in[4], (const float*)d_in[8],  (const float*)d_in[12]};
    const float* b2[3] = {(const float*)d_in[5], (const float*)d_in[9],  (const float*)d_in[13]};
    const float* wf = (const float*)d_in[14];
    const float* bf = (const float*)d_in[15];
    float* out = (float*)d_out;

    float *bufA, *bufB;
    cudaGetSymbolAddress((void**)&bufA, g_bufA);
    cudaGetSymbolAddress((void**)&bufB, g_bufB);

    const int SMEM = SMEM_TOTAL_WORDS * 4;   // ~99.6 KB
    static bool attr_done = false;
    if (!attr_done) {
        cudaFuncSetAttribute(block_kernel<true, true, true>,
                             cudaFuncAttributeMaxDynamicSharedMemorySize, SMEM);
        cudaFuncSetAttribute(block_kernel<false, false, false>,
                             cudaFuncAttributeMaxDynamicSharedMemorySize, SMEM);
        attr_done = true;
    }

    const int EDGE_GRID = (EE + 255) / 256;
    const int MLP_GRID  = (NN + 255) / 256;   // 256 rows per CTA

    // CSR build (deterministic per-launch rebuild; graph-capture safe)
    zero_deg_kernel<<<(NN + 255) / 256, 256>>>();
    hist_kernel<<<EDGE_GRID, 256>>>(ei);
    scan_kernel<<<1, 1024>>>();
    fill_kernel<<<EDGE_GRID, 256>>>(ei);

    // 3 fused GIN blocks + final linear
    block_kernel<true, true, true><<<MLP_GRID, 256, SMEM>>>(x,    bufA, w1[0], b1[0], w2[0], b2[0]);
    block_kernel<true, true, true><<<MLP_GRID, 256, SMEM>>>(bufA, bufB, w1[1], b1[1], w2[1], b2[1]);
    block_kernel<true, true, true><<<MLP_GRID, 256, SMEM>>>(bufB, bufA, w1[2], b1[2], w2[2], b2[2]);
    block_kernel<false, false, false><<<MLP_GRID, 256, SMEM>>>(bufA, out, wf, bf, wf, bf);
}

// round 6
// speedup vs baseline: 1.3001x; 1.3001x over previous
#include <cuda_runtime.h>
#include <cstdint>

#define NN 100000
#define DD 64
#define EE 1600000

// Scratch (__device__ globals per allocation-free rule).
__device__ float g_agg [NN * DD];
__device__ float g_bufA[NN * DD];
__device__ float g_bufB[NN * DD];
__device__ int   g_deg   [NN];
__device__ int   g_rowptr[NN + 1];
__device__ int   g_cursor[NN];
__device__ int   g_col   [EE];

typedef unsigned long long ull;
__device__ __forceinline__ ull pack2(float a, float b) {
    ull r; asm("mov.b64 %0, {%1, %2};" : "=l"(r) : "f"(a), "f"(b)); return r;
}
__device__ __forceinline__ void unpack2(ull v, float& a, float& b) {
    asm("mov.b64 {%0, %1}, %2;" : "=f"(a), "=f"(b) : "l"(v));
}
__device__ __forceinline__ ull fma2(ull a, ull b, ull c) {
    ull r; asm("fma.rn.f32x2 %0, %1, %2, %3;" : "=l"(r) : "l"(a), "l"(b), "l"(c)); return r;
}

// ---------------------------------------------------------------------------
// CSR build
// ---------------------------------------------------------------------------
__global__ void zero_deg_kernel() {
    int i = blockIdx.x * blockDim.x + threadIdx.x;
    if (i < NN) g_deg[i] = 0;
}

__global__ void hist_kernel(const int* __restrict__ ei) {
    int e = blockIdx.x * blockDim.x + threadIdx.x;
    if (e < EE) atomicAdd(&g_deg[ei[EE + e]], 1);
}

__global__ void scan_kernel() {
    __shared__ int sums[1024];
    const int CH = (NN + 1023) / 1024;
    int t = threadIdx.x;
    int base = t * CH;
    int s = 0;
    for (int i = 0; i < CH; i++) {
        int idx = base + i;
        if (idx < NN) s += g_deg[idx];
    }
    sums[t] = s;
    __syncthreads();
    for (int off = 1; off < 1024; off <<= 1) {
        int v = (t >= off) ? sums[t - off] : 0;
        __syncthreads();
        sums[t] += v;
        __syncthreads();
    }
    int prefix = (t == 0) ? 0 : sums[t - 1];
    for (int i = 0; i < CH; i++) {
        int idx = base + i;
        if (idx < NN) {
            int d = g_deg[idx];
            g_rowptr[idx] = prefix;
            g_cursor[idx] = prefix;
            prefix += d;
        }
    }
    if (t == 1023) g_rowptr[NN] = prefix;
}

__global__ void fill_kernel(const int* __restrict__ ei) {
    int e = blockIdx.x * blockDim.x + threadIdx.x;
    if (e < EE) {
        int d = ei[EE + e];
        int p = atomicAdd(&g_cursor[d], 1);
        g_col[p] = ei[e];
    }
}

// ---------------------------------------------------------------------------
// Aggregation gather: warp per dst node, MLP=4 via manual unroll-by-4 with
// 4 independent float2 accumulators. Lane covers bytes [8*lane, 8*lane+8).
//   out[d] = in[d] + sum_{s in CSR(d)} in[s]
// ---------------------------------------------------------------------------
__global__ __launch_bounds__(256) void agg_kernel(const float* __restrict__ in,
                                                  float* __restrict__ out) {
    int w    = (blockIdx.x * blockDim.x + threadIdx.x) >> 5;
    int lane = threadIdx.x & 31;
    if (w >= NN) return;
    int start = g_rowptr[w];
    int end   = g_rowptr[w + 1];

    const float2* in2 = reinterpret_cast<const float2*>(in);
    float2 a0 = in2[(size_t)w * 32 + lane];
    float2 a1 = make_float2(0.f, 0.f);
    float2 a2 = make_float2(0.f, 0.f);
    float2 a3 = make_float2(0.f, 0.f);

    for (int i = start; i < end; i += 32) {
        int n   = min(32, end - i);
        int idx = (i + lane < end) ? g_col[i + lane] : 0;
        int j = 0;
        for (; j + 4 <= n; j += 4) {
            int s0 = __shfl_sync(0xffffffffu, idx, j);
            int s1 = __shfl_sync(0xffffffffu, idx, j + 1);
            int s2 = __shfl_sync(0xffffffffu, idx, j + 2);
            int s3 = __shfl_sync(0xffffffffu, idx, j + 3);
            float2 v0 = in2[(size_t)s0 * 32 + lane];
            float2 v1 = in2[(size_t)s1 * 32 + lane];
            float2 v2 = in2[(size_t)s2 * 32 + lane];
            float2 v3 = in2[(size_t)s3 * 32 + lane];
            a0.x += v0.x; a0.y += v0.y;
            a1.x += v1.x; a1.y += v1.y;
            a2.x += v2.x; a2.y += v2.y;
            a3.x += v3.x; a3.y += v3.y;
        }
        for (; j < n; j++) {
            int s = __shfl_sync(0xffffffffu, idx, j);
            float2 v = in2[(size_t)s * 32 + lane];
            a0.x += v.x; a0.y += v.y;
        }
    }
    a0.x += a1.x + a2.x + a3.x;
    a0.y += a1.y + a2.y + a3.y;
    reinterpret_cast<float2*>(out)[(size_t)w * 32 + lane] = a0;
}

// ---------------------------------------------------------------------------
// MLP kernel (spill-free): lane owns one full row; 32 rows/warp staged through
// padded smem; GEMMs computed in 32-col halves (acc[16] packed f32x2 each).
// ---------------------------------------------------------------------------
#define STRIDE 66
#define STAGE_WORDS (32 * STRIDE)
#define SMEM_TOTAL_WORDS (2 * DD * DD + 8 * STAGE_WORDS)

__device__ __forceinline__ void half_gemm(const float* __restrict__ ws,
                                          const float* __restrict__ h,
                                          ull* acc, int half) {
#pragma unroll 2
    for (int k = 0; k < DD; k++) {
        float hk = h[k];
        ull h2 = pack2(hk, hk);
#pragma unroll
        for (int jj = 0; jj < 8; jj++) {
            float4 wv = *reinterpret_cast<const float4*>(ws + k * DD + half * 32 + jj * 4);
            acc[2 * jj]     = fma2(pack2(wv.x, wv.y), h2, acc[2 * jj]);
            acc[2 * jj + 1] = fma2(pack2(wv.z, wv.w), h2, acc[2 * jj + 1]);
        }
    }
}

template <bool TWO, bool RELU_OUT>
__global__ __launch_bounds__(256, 2) void mlp_kernel(
        const float* __restrict__ in, float* __restrict__ out,
        const float* __restrict__ w1, const float* __restrict__ b1,
        const float* __restrict__ w2, const float* __restrict__ b2) {
    extern __shared__ float sm[];
    float* ws1 = sm;
    float* ws2 = sm + DD * DD;
    int tid  = threadIdx.x;
    int lane = tid & 31;
    int warp = tid >> 5;
    float* stg = sm + 2 * DD * DD + warp * STAGE_WORDS;

    for (int i = tid; i < DD * DD; i += 256) {
        ws1[i] = w1[i];
        if (TWO) ws2[i] = w2[i];
    }

    // stage 32 rows per warp: coalesced float2 loads
    int rowbase = blockIdx.x * 256 + warp * 32;
#pragma unroll 4
    for (int r = 0; r < 32; r++) {
        int row = rowbase + r;
        float2 v = make_float2(0.f, 0.f);
        if (row < NN)
            v = *reinterpret_cast<const float2*>(in + (size_t)row * DD + 2 * lane);
        *reinterpret_cast<float2*>(stg + r * STRIDE + 2 * lane) = v;
    }
    __syncthreads();

    float* hrow = stg + lane * STRIDE;
    const ull* b1u = reinterpret_cast<const ull*>(b1);

    ull mA[16], mB[16];
#pragma unroll
    for (int j = 0; j < 16; j++) mA[j] = b1u[j];
    half_gemm(ws1, hrow, mA, 0);
#pragma unroll
    for (int j = 0; j < 16; j++) mB[j] = b1u[16 + j];
    half_gemm(ws1, hrow, mB, 1);

    if (TWO) {
#pragma unroll
        for (int j = 0; j < 16; j++) {
            float a, b;
            unpack2(mA[j], a, b);
            *reinterpret_cast<float2*>(hrow + 2 * j) =
                make_float2(fmaxf(a, 0.f), fmaxf(b, 0.f));
            unpack2(mB[j], a, b);
            *reinterpret_cast<float2*>(hrow + 32 + 2 * j) =
                make_float2(fmaxf(a, 0.f), fmaxf(b, 0.f));
        }
        const ull* b2u = reinterpret_cast<const ull*>(b2);
#pragma unroll
        for (int j = 0; j < 16; j++) mA[j] = b2u[j];
        half_gemm(ws2, hrow, mA, 0);
#pragma unroll
        for (int j = 0; j < 16; j++) mB[j] = b2u[16 + j];
        half_gemm(ws2, hrow, mB, 1);
    }

#pragma unroll
    for (int j = 0; j < 16; j++) {
        float a, b;
        unpack2(mA[j], a, b);
        if (RELU_OUT) { a = fmaxf(a, 0.f); b = fmaxf(b, 0.f); }
        *reinterpret_cast<float2*>(hrow + 2 * j) = make_float2(a, b);
        unpack2(mB[j], a, b);
        if (RELU_OUT) { a = fmaxf(a, 0.f); b = fmaxf(b, 0.f); }
        *reinterpret_cast<float2*>(hrow + 32 + 2 * j) = make_float2(a, b);
    }
    __syncwarp();
#pragma unroll 4
    for (int r = 0; r < 32; r++) {
        int row = rowbase + r;
        if (row < NN) {
            float2 v = *reinterpret_cast<const float2*>(stg + r * STRIDE + 2 * lane);
            *reinterpret_cast<float2*>(out + (size_t)row * DD + 2 * lane) = v;
        }
    }
}

// ---------------------------------------------------------------------------
// Launch
// ---------------------------------------------------------------------------
extern "C" void kernel_launch(void* const* d_in, const int* in_sizes, int n_in,
                              void* d_out, int out_size) {
    const float* x  = (const float*)d_in[0];
    const int*   ei = (const int*)d_in[1];
    const float* w1[3] = {(const float*)d_in[2], (const float*)d_in[6],  (const float*)d_in[10]};
    const float* b1[3] = {(const float*)d_in[3], (const float*)d_in[7],  (const float*)d_in[11]};
    const float* w2[3] = {(const float*)d_in[4], (const float*)d_in[8],  (const float*)d_in[12]};
    const float* b2[3] = {(const float*)d_in[5], (const float*)d_in[9],  (const float*)d_in[13]};
    const float* wf = (const float*)d_in[14];
    const float* bf = (const float*)d_in[15];
    float* out = (float*)d_out;

    float *agg, *bufA, *bufB;
    cudaGetSymbolAddress((void**)&agg,  g_agg);
    cudaGetSymbolAddress((void**)&bufA, g_bufA);
    cudaGetSymbolAddress((void**)&bufB, g_bufB);

    const int SMEM = SMEM_TOTAL_WORDS * 4;   // ~99.6 KB
    static bool attr_done = false;
    if (!attr_done) {
        cudaFuncSetAttribute(mlp_kernel<true, true>,
                             cudaFuncAttributeMaxDynamicSharedMemorySize, SMEM);
        cudaFuncSetAttribute(mlp_kernel<false, false>,
                             cudaFuncAttributeMaxDynamicSharedMemorySize, SMEM);
        attr_done = true;
    }

    const int EDGE_GRID = (EE + 255) / 256;
    const int AGG_GRID  = (NN * 32 + 255) / 256;
    const int MLP_GRID  = (NN + 255) / 256;

    // CSR build
    zero_deg_kernel<<<(NN + 255) / 256, 256>>>();
    hist_kernel<<<EDGE_GRID, 256>>>(ei);
    scan_kernel<<<1, 1024>>>();
    fill_kernel<<<EDGE_GRID, 256>>>(ei);

    // block 0
    agg_kernel<<<AGG_GRID, 256>>>(x, agg);
    mlp_kernel<true, true><<<MLP_GRID, 256, SMEM>>>(agg, bufA, w1[0], b1[0], w2[0], b2[0]);
    // block 1
    agg_kernel<<<AGG_GRID, 256>>>(bufA, agg);
    mlp_kernel<true, true><<<MLP_GRID, 256, SMEM>>>(agg, bufB, w1[1], b1[1], w2[1], b2[1]);
    // block 2
    agg_kernel<<<AGG_GRID, 256>>>(bufB, agg);
    mlp_kernel<true, true><<<MLP_GRID, 256, SMEM>>>(agg, bufA, w1[2], b1[2], w2[2], b2[2]);
    // final linear
    mlp_kernel<false, false><<<MLP_GRID, 256, SMEM>>>(bufA, out, wf, bf, wf, bf);
}